// round 15
// baseline (speedup 1.0000x reference)
#include <cuda_runtime.h>
#include <cuda_fp16.h>
#include <cstdint>

#define NB 65536

// ============================ device scratch ============================
__device__ int g_cnt[16];
__device__ int g_gidx[16][NB];
// fp16 activations
__device__ __align__(16) __half g_in16[(size_t)NB * 128];
__device__ __align__(16) __half g_h16[(size_t)NB * 256];
__device__ __align__(16) __half g_bA16[(size_t)NB * 384];
__device__ __align__(16) __half g_bB16[(size_t)NB * 384];
__device__ __align__(16) __half g_bC16[(size_t)NB * 384];
// fp16 weights, n-major [e][n][k]
__device__ __align__(16) __half g_wprep[3407872];

// layer offsets into g_wprep (half units)
static const size_t OFF_W0_0 = 0;
static const size_t OFF_W0_1 = 65536;
static const size_t OFF_W1p  = 327680;
static const size_t OFF_W1_0 = 393216;
static const size_t OFF_W1_1 = 1179648;
static const size_t OFF_W2p  = 1441792;
static const size_t OFF_W2_0 = 1507328;
static const size_t OFF_W2_1 = 2293760;
static const size_t OFF_W3p  = 2555904;
static const size_t OFF_W3_0 = 2621440;

// ============================ routing ============================
__global__ void k_zero() { if (threadIdx.x < 16) g_cnt[threadIdx.x] = 0; }

__global__ void k_route(const float* __restrict__ in) {
    int row = blockIdx.x * 256 + threadIdx.x;
    if (row >= NB) return;
    int lane = threadIdx.x & 31;
    const float* oh = in + (size_t)row * 144 + 128;
    #pragma unroll
    for (int j = 0; j < 4; j++) {
        int e = 0;
        #pragma unroll
        for (int t = 1; t < 4; t++) if (oh[j * 4 + t] > 0.5f) e = t;
        #pragma unroll
        for (int ee = 0; ee < 4; ee++) {
            unsigned m = __ballot_sync(0xffffffffu, e == ee);
            if (e == ee) {
                int leader = __ffs(m) - 1, base = 0;
                if (lane == leader) base = atomicAdd(&g_cnt[j * 4 + ee], __popc(m));
                base = __shfl_sync(m, base, leader);
                g_gidx[j * 4 + ee][base + __popc(m & ((1u << lane) - 1u))] = row;
            }
        }
    }
}

// input features [B, 0:128] -> fp16
__global__ void k_cvt(const float* __restrict__ in) {
    int id = blockIdx.x * 256 + threadIdx.x;     // NB*16 segs of 8 floats
    if (id >= NB * 16) return;
    int row = id >> 4, c8 = (id & 15) * 8;
    const float4* p = (const float4*)(in + (size_t)row * 144 + c8);
    float4 v0 = p[0], v1 = p[1];
    unsigned u[4];
    u[0] = ((unsigned)__half_as_ushort(__float2half_rn(v0.y)) << 16) | __half_as_ushort(__float2half_rn(v0.x));
    u[1] = ((unsigned)__half_as_ushort(__float2half_rn(v0.w)) << 16) | __half_as_ushort(__float2half_rn(v0.z));
    u[2] = ((unsigned)__half_as_ushort(__float2half_rn(v1.y)) << 16) | __half_as_ushort(__float2half_rn(v1.x));
    u[3] = ((unsigned)__half_as_ushort(__float2half_rn(v1.w)) << 16) | __half_as_ushort(__float2half_rn(v1.z));
    *(uint4*)(g_in16 + (size_t)row * 128 + c8) = make_uint4(u[0], u[1], u[2], u[3]);
}

// ============================ fused weight prep ============================
struct PrepArgs { const float* W[10]; };
__constant__ int c_in[10]   = {32, 256, 32, 384, 256, 32, 384, 256, 32, 384};
__constant__ int c_out[10]  = {256, 128, 256, 256, 128, 256, 256, 128, 256, 256};
__constant__ int c_cum[10]  = {0, 32768, 163840, 196608, 589824,
                               720896, 753664, 1146880, 1277952, 1310720};
__constant__ size_t c_base[10] = {OFF_W0_0, OFF_W0_1, OFF_W1p, OFF_W1_0, OFF_W1_1,
                                  OFF_W2p, OFF_W2_0, OFF_W2_1, OFF_W3p, OFF_W3_0};
#define PREP_TOTAL 1703936

__global__ void k_prep_all(PrepArgs pa) {
    for (int id = blockIdx.x * 256 + threadIdx.x; id < PREP_TOTAL; id += gridDim.x * 256) {
        int s = 9;
        #pragma unroll
        for (int i = 1; i < 10; i++) if (id < c_cum[i]) { s = i - 1; break; }
        int IN = c_in[s], OUT = c_out[s];
        int local = id - c_cum[s];
        int e = local / (OUT * IN);
        int rem = local % (OUT * IN);
        int n = rem / IN, k = rem % IN;
        float v = pa.W[s][((size_t)e * IN + k) * OUT + n];
        g_wprep[c_base[s] + (size_t)(e * OUT + n) * IN + k] = __float2half_rn(v);
    }
}

// ============================ mma / ldmatrix helpers ============================
#define MMA16816(c, a, b) \
    asm volatile("mma.sync.aligned.m16n8k16.row.col.f32.f16.f16.f32 " \
        "{%0,%1,%2,%3}, {%4,%5,%6,%7}, {%8,%9}, {%0,%1,%2,%3};" \
        : "+f"((c)[0]), "+f"((c)[1]), "+f"((c)[2]), "+f"((c)[3]) \
        : "r"((a)[0]), "r"((a)[1]), "r"((a)[2]), "r"((a)[3]), \
          "r"((b)[0]), "r"((b)[1]))

#define LDSM_X4(r0, r1, r2, r3, addr) \
    asm volatile("ldmatrix.sync.aligned.m8n8.x4.shared.b16 {%0,%1,%2,%3}, [%4];" \
        : "=r"(r0), "=r"(r1), "=r"(r2), "=r"(r3) : "r"(addr) : "memory")

__device__ __forceinline__ uint32_t smem_u32(const void* p) {
    return (uint32_t)__cvta_generic_to_shared(p);
}

// buffer selectors: 0=g_in16, 1=g_h16, 2=bufA, 3=bufB, 4=bufC
__device__ __forceinline__ const __half* selsrc(int s) {
    if (s == 0) return g_in16;
    if (s == 1) return g_h16;
    if (s == 2) return g_bA16;
    if (s == 3) return g_bB16;
    return g_bC16;
}
__device__ __forceinline__ __half* seldst(int s) {
    if (s == 1) return g_h16;
    if (s == 2) return g_bA16;
    if (s == 3) return g_bB16;
    return g_bC16;
}

// ============================ GEMM body ============================
// Block: 128 gathered rows x 128 cols (blockIdx.y = col block). Pure fp16 MMA.
// Double-buffered smem + DEPTH-2 register prefetch (loads issued 2 chunks ahead).
template <int IN, int OUT>
__device__ __forceinline__ void gemm_body(
        int node, int asel, int acol, size_t woff,
        const float* __restrict__ Ball, int csel, int ldc, int ccol) {
    constexpr int SA = 40;               // row stride (halfs); 80B -> LDSM conflict-free
    constexpr int AH = 128 * SA;         // 5120 halfs per tile
    constexpr int BUFH = 2 * AH;         // halfs per buffer (A+B)
    constexpr int BUFB = BUFH * 2;       // bytes per buffer = 20480
    constexpr int NCH = IN / 32;

    extern __shared__ __half dyn[];      // [buf0 A|B][buf1 A|B]
    __shared__ int s_ridx[128];
    __shared__ float s_bias[128];

    const int tid = threadIdx.x;
    const int cb = blockIdx.y;

    // map blockIdx.x -> (expert, tile)
    int e = -1, tile = 0, nrows = 0, acc0 = 0;
    #pragma unroll
    for (int ee = 0; ee < 4; ee++) {
        int ne = g_cnt[node * 4 + ee];
        int nt = (ne + 127) >> 7;
        if (e < 0 && (int)blockIdx.x < acc0 + nt) { e = ee; tile = (int)blockIdx.x - acc0; nrows = ne; }
        acc0 += nt;
    }
    if (e < 0) return;

    if (tid < 128) {
        int r = tile * 128 + tid;
        s_ridx[tid] = (r < nrows) ? g_gidx[node * 4 + e][r] : -1;
        s_bias[tid] = Ball[(size_t)e * OUT + cb * 128 + tid];
    }
    __syncthreads();

    const __half* Aptr = selsrc(asel);
    const int lda = (asel == 0) ? 128 : (asel == 1 ? 256 : 384);
    __half* C = seldst(csel);

    // staging: thread -> row ar (0..127), k-half ak0 (0 or 16 halfs)
    const int ar = tid >> 1, ak0 = (tid & 1) * 16;
    const int ari = s_ridx[ar];
    const __half* abase = Aptr + (size_t)(ari < 0 ? 0 : ari) * lda + acol + ak0;
    const __half* bbase = g_wprep + woff + ((size_t)(e * OUT + cb * 128 + ar) * IN + ak0);

    uint4 av[2][2], bv[2][2];            // two in-flight register sets
    auto ldAB = [&](uint4* a, uint4* b, int kk) {
        if (ari >= 0) {
            const uint4* p = (const uint4*)(abase + kk);
            a[0] = p[0]; a[1] = p[1];
        } else {
            a[0] = a[1] = make_uint4(0, 0, 0, 0);
        }
        const uint4* pb = (const uint4*)(bbase + kk);
        b[0] = pb[0]; b[1] = pb[1];
    };
    auto stAB = [&](const uint4* a, const uint4* b, int buf) {
        __half* r = dyn + buf * BUFH + ar * SA + ak0;
        *(uint4*)r = a[0]; *(uint4*)(r + 8) = a[1];
        __half* rb = dyn + buf * BUFH + AH + ar * SA + ak0;
        *(uint4*)rb = b[0]; *(uint4*)(rb + 8) = b[1];
    };

    // warp layout: 4 (m) x 2 (n); warp tile 32 rows x 64 cols
    const int w = tid >> 5, lane = tid & 31;
    const int m0 = (w >> 1) * 32, n0 = (w & 1) * 64;
    const int g = lane >> 2, t4 = lane & 3;
    const int q = lane >> 3;

    const uint32_t base32 = smem_u32(dyn);
    uint32_t aRel[2], bRel[4];
    #pragma unroll
    for (int ms = 0; ms < 2; ms++)
        aRel[ms] = (uint32_t)(((m0 + ms * 16 + (lane & 7) + (q & 1) * 8) * SA
                               + (q >> 1) * 8) * 2);
    #pragma unroll
    for (int j = 0; j < 4; j++)
        bRel[j] = (uint32_t)((AH + (n0 + (2 * j + (q >> 1)) * 8 + (lane & 7)) * SA
                              + (q & 1) * 8) * 2);

    float acc[2][8][4];
    #pragma unroll
    for (int i = 0; i < 2; i++)
        #pragma unroll
        for (int j = 0; j < 8; j++)
            #pragma unroll
            for (int c = 0; c < 4; c++) acc[i][j][c] = 0.f;

    // depth-2 pipeline:
    //   chunk t's regs: loaded at t-2, staged (STS) at end of t-1, MMA'd at t.
    ldAB(av[0], bv[0], 0);
    if (NCH > 1) ldAB(av[1], bv[1], 32);
    stAB(av[0], bv[0], 0);
    __syncthreads();
    for (int ch = 0; ch < NCH; ch++) {
        if (ch + 2 < NCH) ldAB(av[ch & 1], bv[ch & 1], (ch + 2) * 32);
        const uint32_t bufb = base32 + (uint32_t)(ch & 1) * BUFB;
        #pragma unroll
        for (int ks = 0; ks < 2; ks++) {
            const uint32_t kb = ks * 32;     // 16 halfs = 32 bytes
            unsigned a[2][4], b[8][2];
            #pragma unroll
            for (int ms = 0; ms < 2; ms++)
                LDSM_X4(a[ms][0], a[ms][1], a[ms][2], a[ms][3],
                        bufb + aRel[ms] + kb);
            #pragma unroll
            for (int j = 0; j < 4; j++)
                LDSM_X4(b[2 * j][0], b[2 * j][1], b[2 * j + 1][0], b[2 * j + 1][1],
                        bufb + bRel[j] + kb);
            #pragma unroll
            for (int ms = 0; ms < 2; ms++)
                #pragma unroll
                for (int ns = 0; ns < 8; ns++)
                    MMA16816(acc[ms][ns], a[ms], b[ns]);
        }
        if (ch + 1 < NCH) stAB(av[(ch + 1) & 1], bv[(ch + 1) & 1], (ch + 1) & 1);
        __syncthreads();
    }

    // epilogue (R10-proven): bias + relu -> fp16, direct scatter
    #pragma unroll
    for (int ms = 0; ms < 2; ms++) {
        int r0 = m0 + ms * 16 + g;
        int ri = s_ridx[r0], rj = s_ridx[r0 + 8];
        __half* c0p = C + (size_t)(ri < 0 ? 0 : ri) * ldc + ccol + cb * 128;
        __half* c1p = C + (size_t)(rj < 0 ? 0 : rj) * ldc + ccol + cb * 128;
        #pragma unroll
        for (int ns = 0; ns < 8; ns++) {
            int cc = n0 + ns * 8 + 2 * t4;
            float b0 = s_bias[cc], b1 = s_bias[cc + 1];
            if (ri >= 0) {
                __half2 v = __floats2half2_rn(fmaxf(acc[ms][ns][0] + b0, 0.f),
                                              fmaxf(acc[ms][ns][1] + b1, 0.f));
                *(__half2*)(c0p + cc) = v;
            }
            if (rj >= 0) {
                __half2 v = __floats2half2_rn(fmaxf(acc[ms][ns][2] + b0, 0.f),
                                              fmaxf(acc[ms][ns][3] + b1, 0.f));
                *(__half2*)(c1p + cc) = v;
            }
        }
    }
}

// ============================ kernels ============================
template <int IN, int OUT>
__global__ __launch_bounds__(256) void k_tgemm(
        int node, int asel, size_t woff, const float* __restrict__ Ball,
        int csel, int ldc, int ccol) {
    gemm_body<IN, OUT>(node, asel, 0, woff, Ball, csel, ldc, ccol);
}

// fused input-side GEMMs: z=0 node0 main; z=1..3 pre layers (independent)
struct PreArgs { const float* bias[4]; };
__global__ __launch_bounds__(256) void k_pre(PreArgs pa) {
    int z = blockIdx.z;
    size_t woff = (z == 0) ? OFF_W0_0 : (z == 1) ? OFF_W1p : (z == 2) ? OFF_W2p : OFF_W3p;
    int csel = (z == 0) ? 1 : (z + 1);            // g_h16, bufA, bufB, bufC
    int ldc  = (z == 0) ? 256 : 384;
    int ccol = (z == 0) ? 0 : 128;
    gemm_body<32, 256>(z, 0, z * 32, woff, pa.bias[z], csel, ldc, ccol);
}

// ============================ final 256->8 head (no relu) ============================
__global__ __launch_bounds__(256) void k_final(
        const float* __restrict__ in, const float* __restrict__ W,
        const float* __restrict__ Bb, float* __restrict__ out) {
    int gw = (blockIdx.x * 256 + threadIdx.x) >> 5;
    int lane = threadIdx.x & 31;
    if (gw >= NB) return;
    const float* oh = in + (size_t)gw * 144 + 140;
    int e = 0;
    #pragma unroll
    for (int t = 1; t < 4; t++) if (oh[t] > 0.5f) e = t;
    const __half* h = g_h16 + (size_t)gw * 256;
    const float* w = W + (size_t)e * 2048;
    float acc[8] = {0, 0, 0, 0, 0, 0, 0, 0};
    #pragma unroll
    for (int kk = 0; kk < 256; kk += 32) {
        int k = kk + lane;
        float hv = __half2float(h[k]);
        float4 wa = *(const float4*)(w + k * 8);
        float4 wb = *(const float4*)(w + k * 8 + 4);
        acc[0] += hv * wa.x; acc[1] += hv * wa.y; acc[2] += hv * wa.z; acc[3] += hv * wa.w;
        acc[4] += hv * wb.x; acc[5] += hv * wb.y; acc[6] += hv * wb.z; acc[7] += hv * wb.w;
    }
    #pragma unroll
    for (int o = 16; o > 0; o >>= 1)
        #pragma unroll
        for (int c = 0; c < 8; c++) acc[c] += __shfl_xor_sync(0xffffffffu, acc[c], o);
    if (lane < 8) {
        float v = acc[0];
        switch (lane) {
            case 1: v = acc[1]; break; case 2: v = acc[2]; break;
            case 3: v = acc[3]; break; case 4: v = acc[4]; break;
            case 5: v = acc[5]; break; case 6: v = acc[6]; break;
            case 7: v = acc[7]; break; default: break;
        }
        out[(size_t)gw * 8 + lane] = v + Bb[e * 8 + lane];
    }
}

// ============================ launch ============================
extern "C" void kernel_launch(void* const* d_in, const int* in_sizes, int n_in,
                              void* d_out, int out_size) {
    const float* in = (const float*)d_in[0];
    float* out = (float*)d_out;
    auto P = [&](int i) { return (const float*)d_in[i]; };

    const int DSM = 2 * 20480;   // 40960 B: double-buffered A+B
    cudaFuncSetAttribute((const void*)k_tgemm<256, 128>,
                         cudaFuncAttributeMaxDynamicSharedMemorySize, DSM);
    cudaFuncSetAttribute((const void*)k_tgemm<384, 256>,
                         cudaFuncAttributeMaxDynamicSharedMemorySize, DSM);
    cudaFuncSetAttribute((const void*)k_pre,
                         cudaFuncAttributeMaxDynamicSharedMemorySize, DSM);

    PrepArgs pa;
    pa.W[0] = P(1);  pa.W[1] = P(3);  pa.W[2] = P(5);  pa.W[3] = P(7);  pa.W[4] = P(9);
    pa.W[5] = P(11); pa.W[6] = P(13); pa.W[7] = P(15); pa.W[8] = P(17); pa.W[9] = P(19);
    k_prep_all<<<1024, 256>>>(pa);

    k_zero<<<1, 16>>>();
    k_route<<<NB / 256, 256>>>(in);
    k_cvt<<<NB * 16 / 256, 256>>>(in);

    // fused input-side layers: node0 main -> g_h16 ; pre1/2/3 -> bufA/B/C[128:384]
    PreArgs pr;
    pr.bias[0] = P(2); pr.bias[1] = P(6); pr.bias[2] = P(12); pr.bias[3] = P(18);
    k_pre<<<dim3(516, 2, 4), 256, DSM>>>(pr);

    // node 0 proj: g_h16 -> bufA[0:128]
    k_tgemm<256, 128><<<dim3(516, 1), 256, DSM>>>(0, 1, OFF_W0_1, P(4),  2, 384, 0);
    // node 1 main: bufA -> g_h16 ; proj: g_h16 -> bufB[0:128]
    k_tgemm<384, 256><<<dim3(516, 2), 256, DSM>>>(1, 2, OFF_W1_0, P(8),  1, 256, 0);
    k_tgemm<256, 128><<<dim3(516, 1), 256, DSM>>>(1, 1, OFF_W1_1, P(10), 3, 384, 0);
    // node 2 main: bufB -> g_h16 ; proj: g_h16 -> bufC[0:128]
    k_tgemm<384, 256><<<dim3(516, 2), 256, DSM>>>(2, 3, OFF_W2_0, P(14), 1, 256, 0);
    k_tgemm<256, 128><<<dim3(516, 1), 256, DSM>>>(2, 1, OFF_W2_1, P(16), 4, 384, 0);
    // node 3 main: bufC -> g_h16
    k_tgemm<384, 256><<<dim3(516, 2), 256, DSM>>>(3, 4, OFF_W3_0, P(20), 1, 256, 0);
    // final head
    k_final<<<NB / 8, 256>>>(in, P(21), P(22), out);
}

// round 16
// speedup vs baseline: 1.1526x; 1.1526x over previous
#include <cuda_runtime.h>
#include <cuda_fp16.h>
#include <cstdint>

#define NB 65536

// ============================ device scratch ============================
__device__ int g_cnt[16];
__device__ int g_gidx[16][NB];
// fp16 activations
__device__ __align__(16) __half g_in16[(size_t)NB * 128];
__device__ __align__(16) __half g_h16[(size_t)NB * 256];
__device__ __align__(16) __half g_bA16[(size_t)NB * 384];
__device__ __align__(16) __half g_bB16[(size_t)NB * 384];
__device__ __align__(16) __half g_bC16[(size_t)NB * 384];
// fp16 weights, n-major [e][n][k]
__device__ __align__(16) __half g_wprep[3407872];

// layer offsets into g_wprep (half units)
static const size_t OFF_W0_0 = 0;
static const size_t OFF_W0_1 = 65536;
static const size_t OFF_W1p  = 327680;
static const size_t OFF_W1_0 = 393216;
static const size_t OFF_W1_1 = 1179648;
static const size_t OFF_W2p  = 1441792;
static const size_t OFF_W2_0 = 1507328;
static const size_t OFF_W2_1 = 2293760;
static const size_t OFF_W3p  = 2555904;
static const size_t OFF_W3_0 = 2621440;

// ============================ routing ============================
__global__ void k_zero() { if (threadIdx.x < 16) g_cnt[threadIdx.x] = 0; }

__global__ void k_route(const float* __restrict__ in) {
    int row = blockIdx.x * 256 + threadIdx.x;
    if (row >= NB) return;
    int lane = threadIdx.x & 31;
    const float* oh = in + (size_t)row * 144 + 128;
    #pragma unroll
    for (int j = 0; j < 4; j++) {
        int e = 0;
        #pragma unroll
        for (int t = 1; t < 4; t++) if (oh[j * 4 + t] > 0.5f) e = t;
        #pragma unroll
        for (int ee = 0; ee < 4; ee++) {
            unsigned m = __ballot_sync(0xffffffffu, e == ee);
            if (e == ee) {
                int leader = __ffs(m) - 1, base = 0;
                if (lane == leader) base = atomicAdd(&g_cnt[j * 4 + ee], __popc(m));
                base = __shfl_sync(m, base, leader);
                g_gidx[j * 4 + ee][base + __popc(m & ((1u << lane) - 1u))] = row;
            }
        }
    }
}

// input features [B, 0:128] -> fp16
__global__ void k_cvt(const float* __restrict__ in) {
    int id = blockIdx.x * 256 + threadIdx.x;     // NB*16 segs of 8 floats
    if (id >= NB * 16) return;
    int row = id >> 4, c8 = (id & 15) * 8;
    const float4* p = (const float4*)(in + (size_t)row * 144 + c8);
    float4 v0 = p[0], v1 = p[1];
    unsigned u[4];
    u[0] = ((unsigned)__half_as_ushort(__float2half_rn(v0.y)) << 16) | __half_as_ushort(__float2half_rn(v0.x));
    u[1] = ((unsigned)__half_as_ushort(__float2half_rn(v0.w)) << 16) | __half_as_ushort(__float2half_rn(v0.z));
    u[2] = ((unsigned)__half_as_ushort(__float2half_rn(v1.y)) << 16) | __half_as_ushort(__float2half_rn(v1.x));
    u[3] = ((unsigned)__half_as_ushort(__float2half_rn(v1.w)) << 16) | __half_as_ushort(__float2half_rn(v1.z));
    *(uint4*)(g_in16 + (size_t)row * 128 + c8) = make_uint4(u[0], u[1], u[2], u[3]);
}

// ============================ fused weight prep ============================
struct PrepArgs { const float* W[10]; };
__constant__ int c_in[10]   = {32, 256, 32, 384, 256, 32, 384, 256, 32, 384};
__constant__ int c_out[10]  = {256, 128, 256, 256, 128, 256, 256, 128, 256, 256};
__constant__ int c_cum[10]  = {0, 32768, 163840, 196608, 589824,
                               720896, 753664, 1146880, 1277952, 1310720};
__constant__ size_t c_base[10] = {OFF_W0_0, OFF_W0_1, OFF_W1p, OFF_W1_0, OFF_W1_1,
                                  OFF_W2p, OFF_W2_0, OFF_W2_1, OFF_W3p, OFF_W3_0};
#define PREP_TOTAL 1703936

__global__ void k_prep_all(PrepArgs pa) {
    for (int id = blockIdx.x * 256 + threadIdx.x; id < PREP_TOTAL; id += gridDim.x * 256) {
        int s = 9;
        #pragma unroll
        for (int i = 1; i < 10; i++) if (id < c_cum[i]) { s = i - 1; break; }
        int IN = c_in[s], OUT = c_out[s];
        int local = id - c_cum[s];
        int e = local / (OUT * IN);
        int rem = local % (OUT * IN);
        int n = rem / IN, k = rem % IN;
        float v = pa.W[s][((size_t)e * IN + k) * OUT + n];
        g_wprep[c_base[s] + (size_t)(e * OUT + n) * IN + k] = __float2half_rn(v);
    }
}

// ============================ mma / ldmatrix helpers ============================
#define MMA16816(c, a, b) \
    asm volatile("mma.sync.aligned.m16n8k16.row.col.f32.f16.f16.f32 " \
        "{%0,%1,%2,%3}, {%4,%5,%6,%7}, {%8,%9}, {%0,%1,%2,%3};" \
        : "+f"((c)[0]), "+f"((c)[1]), "+f"((c)[2]), "+f"((c)[3]) \
        : "r"((a)[0]), "r"((a)[1]), "r"((a)[2]), "r"((a)[3]), \
          "r"((b)[0]), "r"((b)[1]))

#define LDSM_X4(r0, r1, r2, r3, addr) \
    asm volatile("ldmatrix.sync.aligned.m8n8.x4.shared.b16 {%0,%1,%2,%3}, [%4];" \
        : "=r"(r0), "=r"(r1), "=r"(r2), "=r"(r3) : "r"(addr) : "memory")

__device__ __forceinline__ uint32_t smem_u32(const void* p) {
    return (uint32_t)__cvta_generic_to_shared(p);
}

// buffer selectors: 0=g_in16, 1=g_h16, 2=bufA, 3=bufB, 4=bufC
__device__ __forceinline__ const __half* selsrc(int s) {
    if (s == 0) return g_in16;
    if (s == 1) return g_h16;
    if (s == 2) return g_bA16;
    if (s == 3) return g_bB16;
    return g_bC16;
}
__device__ __forceinline__ __half* seldst(int s) {
    if (s == 1) return g_h16;
    if (s == 2) return g_bA16;
    if (s == 3) return g_bB16;
    return g_bC16;
}

// ============================ GEMM body ============================
// Block: 128 gathered rows x 128 cols (blockIdx.y = col block). Pure fp16 MMA.
// Single-buffered (R10-proven order), k-chunk = BK (64 for big layers, 32 for IN=32).
// smem: A 128 x (BK+8) halfs, B 128 x (BK+8) halfs; stride conflict-free for LDSM.
template <int IN, int OUT, int BK>
__device__ __forceinline__ void gemm_body(
        int node, int asel, int acol, size_t woff,
        const float* __restrict__ Ball, int csel, int ldc, int ccol) {
    constexpr int SA = BK + 8;           // 40 or 72 halfs; both LDSM conflict-free
    constexpr int AH = 128 * SA;         // halfs per tile
    constexpr int NCH = IN / BK;
    constexpr int NV = BK / 16;          // uint4 per thread per tile (2 or 4)
    constexpr int KH = BK / 2;           // halfs per thread-half (16 or 32)

    extern __shared__ __half dyn[];      // [A | B]
    __shared__ int s_ridx[128];
    __shared__ float s_bias[128];

    const int tid = threadIdx.x;
    const int cb = blockIdx.y;

    // map blockIdx.x -> (expert, tile)
    int e = -1, tile = 0, nrows = 0, acc0 = 0;
    #pragma unroll
    for (int ee = 0; ee < 4; ee++) {
        int ne = g_cnt[node * 4 + ee];
        int nt = (ne + 127) >> 7;
        if (e < 0 && (int)blockIdx.x < acc0 + nt) { e = ee; tile = (int)blockIdx.x - acc0; nrows = ne; }
        acc0 += nt;
    }
    if (e < 0) return;

    if (tid < 128) {
        int r = tile * 128 + tid;
        s_ridx[tid] = (r < nrows) ? g_gidx[node * 4 + e][r] : -1;
        s_bias[tid] = Ball[(size_t)e * OUT + cb * 128 + tid];
    }
    __syncthreads();

    const __half* Aptr = selsrc(asel);
    const int lda = (asel == 0) ? 128 : (asel == 1 ? 256 : 384);
    __half* C = seldst(csel);

    // staging: thread -> row ar (0..127), k-half ak0 (0 or KH halfs)
    const int ar = tid >> 1, ak0 = (tid & 1) * KH;
    const int ari = s_ridx[ar];
    const __half* abase = Aptr + (size_t)(ari < 0 ? 0 : ari) * lda + acol + ak0;
    const __half* bbase = g_wprep + woff + ((size_t)(e * OUT + cb * 128 + ar) * IN + ak0);

    uint4 av[NV], bv[NV];
    auto ldA = [&](int kk) {
        if (ari >= 0) {
            const uint4* p = (const uint4*)(abase + kk);
            #pragma unroll
            for (int i = 0; i < NV; i++) av[i] = p[i];
        } else {
            #pragma unroll
            for (int i = 0; i < NV; i++) av[i] = make_uint4(0, 0, 0, 0);
        }
    };
    auto ldB = [&](int kk) {
        const uint4* p = (const uint4*)(bbase + kk);
        #pragma unroll
        for (int i = 0; i < NV; i++) bv[i] = p[i];
    };
    auto stA = [&]() {
        __half* r = dyn + ar * SA + ak0;
        #pragma unroll
        for (int i = 0; i < NV; i++) *((uint4*)r + i) = av[i];
    };
    auto stB = [&]() {
        __half* r = dyn + AH + ar * SA + ak0;
        #pragma unroll
        for (int i = 0; i < NV; i++) *((uint4*)r + i) = bv[i];
    };

    // warp layout: 4 (m) x 2 (n); warp tile 32 rows x 64 cols
    const int w = tid >> 5, lane = tid & 31;
    const int m0 = (w >> 1) * 32, n0 = (w & 1) * 64;
    const int g = lane >> 2, t4 = lane & 3;
    const int q = lane >> 3;

    const uint32_t base32 = smem_u32(dyn);
    uint32_t aRel[2], bRel[4];
    #pragma unroll
    for (int ms = 0; ms < 2; ms++)
        aRel[ms] = (uint32_t)(((m0 + ms * 16 + (lane & 7) + (q & 1) * 8) * SA
                               + (q >> 1) * 8) * 2);
    #pragma unroll
    for (int j = 0; j < 4; j++)
        bRel[j] = (uint32_t)((AH + (n0 + (2 * j + (q >> 1)) * 8 + (lane & 7)) * SA
                              + (q & 1) * 8) * 2);

    float acc[2][8][4];
    #pragma unroll
    for (int i = 0; i < 2; i++)
        #pragma unroll
        for (int j = 0; j < 8; j++)
            #pragma unroll
            for (int c = 0; c < 4; c++) acc[i][j][c] = 0.f;

    // R10-proven single-buffer pipeline: stage, prefetch-next, sync, MMA, sync
    ldA(0); ldB(0);
    for (int ch = 0; ch < NCH; ch++) {
        stA(); stB();
        if (ch + 1 < NCH) { ldA((ch + 1) * BK); ldB((ch + 1) * BK); }
        __syncthreads();
        #pragma unroll
        for (int ks = 0; ks < BK / 16; ks++) {
            const uint32_t kb = ks * 32;     // 16 halfs = 32 bytes
            unsigned a[2][4], b[8][2];
            #pragma unroll
            for (int ms = 0; ms < 2; ms++)
                LDSM_X4(a[ms][0], a[ms][1], a[ms][2], a[ms][3],
                        base32 + aRel[ms] + kb);
            #pragma unroll
            for (int j = 0; j < 4; j++)
                LDSM_X4(b[2 * j][0], b[2 * j][1], b[2 * j + 1][0], b[2 * j + 1][1],
                        base32 + bRel[j] + kb);
            #pragma unroll
            for (int ms = 0; ms < 2; ms++)
                #pragma unroll
                for (int ns = 0; ns < 8; ns++)
                    MMA16816(acc[ms][ns], a[ms], b[ns]);
        }
        __syncthreads();
    }

    // epilogue (R10-proven): bias + relu -> fp16, direct scatter
    #pragma unroll
    for (int ms = 0; ms < 2; ms++) {
        int r0 = m0 + ms * 16 + g;
        int ri = s_ridx[r0], rj = s_ridx[r0 + 8];
        __half* c0p = C + (size_t)(ri < 0 ? 0 : ri) * ldc + ccol + cb * 128;
        __half* c1p = C + (size_t)(rj < 0 ? 0 : rj) * ldc + ccol + cb * 128;
        #pragma unroll
        for (int ns = 0; ns < 8; ns++) {
            int cc = n0 + ns * 8 + 2 * t4;
            float b0 = s_bias[cc], b1 = s_bias[cc + 1];
            if (ri >= 0) {
                __half2 v = __floats2half2_rn(fmaxf(acc[ms][ns][0] + b0, 0.f),
                                              fmaxf(acc[ms][ns][1] + b1, 0.f));
                *(__half2*)(c0p + cc) = v;
            }
            if (rj >= 0) {
                __half2 v = __floats2half2_rn(fmaxf(acc[ms][ns][2] + b0, 0.f),
                                              fmaxf(acc[ms][ns][3] + b1, 0.f));
                *(__half2*)(c1p + cc) = v;
            }
        }
    }
}

// ============================ kernels ============================
template <int IN, int OUT>
__global__ __launch_bounds__(256) void k_tgemm(
        int node, int asel, size_t woff, const float* __restrict__ Ball,
        int csel, int ldc, int ccol) {
    gemm_body<IN, OUT, 64>(node, asel, 0, woff, Ball, csel, ldc, ccol);
}

// fused input-side GEMMs: z=0 node0 main; z=1..3 pre layers (independent). BK=32.
struct PreArgs { const float* bias[4]; };
__global__ __launch_bounds__(256) void k_pre(PreArgs pa) {
    int z = blockIdx.z;
    size_t woff = (z == 0) ? OFF_W0_0 : (z == 1) ? OFF_W1p : (z == 2) ? OFF_W2p : OFF_W3p;
    int csel = (z == 0) ? 1 : (z + 1);            // g_h16, bufA, bufB, bufC
    int ldc  = (z == 0) ? 256 : 384;
    int ccol = (z == 0) ? 0 : 128;
    gemm_body<32, 256, 32>(z, 0, z * 32, woff, pa.bias[z], csel, ldc, ccol);
}

// ============================ final 256->8 head (no relu) ============================
__global__ __launch_bounds__(256) void k_final(
        const float* __restrict__ in, const float* __restrict__ W,
        const float* __restrict__ Bb, float* __restrict__ out) {
    int gw = (blockIdx.x * 256 + threadIdx.x) >> 5;
    int lane = threadIdx.x & 31;
    if (gw >= NB) return;
    const float* oh = in + (size_t)gw * 144 + 140;
    int e = 0;
    #pragma unroll
    for (int t = 1; t < 4; t++) if (oh[t] > 0.5f) e = t;
    const __half* h = g_h16 + (size_t)gw * 256;
    const float* w = W + (size_t)e * 2048;
    float acc[8] = {0, 0, 0, 0, 0, 0, 0, 0};
    #pragma unroll
    for (int kk = 0; kk < 256; kk += 32) {
        int k = kk + lane;
        float hv = __half2float(h[k]);
        float4 wa = *(const float4*)(w + k * 8);
        float4 wb = *(const float4*)(w + k * 8 + 4);
        acc[0] += hv * wa.x; acc[1] += hv * wa.y; acc[2] += hv * wa.z; acc[3] += hv * wa.w;
        acc[4] += hv * wb.x; acc[5] += hv * wb.y; acc[6] += hv * wb.z; acc[7] += hv * wb.w;
    }
    #pragma unroll
    for (int o = 16; o > 0; o >>= 1)
        #pragma unroll
        for (int c = 0; c < 8; c++) acc[c] += __shfl_xor_sync(0xffffffffu, acc[c], o);
    if (lane < 8) {
        float v = acc[0];
        switch (lane) {
            case 1: v = acc[1]; break; case 2: v = acc[2]; break;
            case 3: v = acc[3]; break; case 4: v = acc[4]; break;
            case 5: v = acc[5]; break; case 6: v = acc[6]; break;
            case 7: v = acc[7]; break; default: break;
        }
        out[(size_t)gw * 8 + lane] = v + Bb[e * 8 + lane];
    }
}

// ============================ launch ============================
extern "C" void kernel_launch(void* const* d_in, const int* in_sizes, int n_in,
                              void* d_out, int out_size) {
    const float* in = (const float*)d_in[0];
    float* out = (float*)d_out;
    auto P = [&](int i) { return (const float*)d_in[i]; };

    const int DSM64 = 2 * 128 * 72 * 2;   // 36864 B (BK=64 tiles)
    const int DSM32 = 2 * 128 * 40 * 2;   // 20480 B (BK=32 tiles, k_pre)
    cudaFuncSetAttribute((const void*)k_tgemm<256, 128>,
                         cudaFuncAttributeMaxDynamicSharedMemorySize, DSM64);
    cudaFuncSetAttribute((const void*)k_tgemm<384, 256>,
                         cudaFuncAttributeMaxDynamicSharedMemorySize, DSM64);
    cudaFuncSetAttribute((const void*)k_pre,
                         cudaFuncAttributeMaxDynamicSharedMemorySize, DSM32);

    PrepArgs pa;
    pa.W[0] = P(1);  pa.W[1] = P(3);  pa.W[2] = P(5);  pa.W[3] = P(7);  pa.W[4] = P(9);
    pa.W[5] = P(11); pa.W[6] = P(13); pa.W[7] = P(15); pa.W[8] = P(17); pa.W[9] = P(19);
    k_prep_all<<<1024, 256>>>(pa);

    k_zero<<<1, 16>>>();
    k_route<<<NB / 256, 256>>>(in);
    k_cvt<<<NB * 16 / 256, 256>>>(in);

    // fused input-side layers: node0 main -> g_h16 ; pre1/2/3 -> bufA/B/C[128:384]
    PreArgs pr;
    pr.bias[0] = P(2); pr.bias[1] = P(6); pr.bias[2] = P(12); pr.bias[3] = P(18);
    k_pre<<<dim3(516, 2, 4), 256, DSM32>>>(pr);

    // node 0 proj: g_h16 -> bufA[0:128]
    k_tgemm<256, 128><<<dim3(516, 1), 256, DSM64>>>(0, 1, OFF_W0_1, P(4),  2, 384, 0);
    // node 1 main: bufA -> g_h16 ; proj: g_h16 -> bufB[0:128]
    k_tgemm<384, 256><<<dim3(516, 2), 256, DSM64>>>(1, 2, OFF_W1_0, P(8),  1, 256, 0);
    k_tgemm<256, 128><<<dim3(516, 1), 256, DSM64>>>(1, 1, OFF_W1_1, P(10), 3, 384, 0);
    // node 2 main: bufB -> g_h16 ; proj: g_h16 -> bufC[0:128]
    k_tgemm<384, 256><<<dim3(516, 2), 256, DSM64>>>(2, 3, OFF_W2_0, P(14), 1, 256, 0);
    k_tgemm<256, 128><<<dim3(516, 1), 256, DSM64>>>(2, 1, OFF_W2_1, P(16), 4, 384, 0);
    // node 3 main: bufC -> g_h16
    k_tgemm<384, 256><<<dim3(516, 2), 256, DSM64>>>(3, 4, OFF_W3_0, P(20), 1, 256, 0);
    // final head
    k_final<<<NB / 8, 256>>>(in, P(21), P(22), out);
}